// round 2
// baseline (speedup 1.0000x reference)
#include <cuda_runtime.h>
#include <math.h>

#define NN 50000
#define EE 800000
#define DD 128
#define NB ((NN + 255) / 256)   // scan blocks

// ---------------- scratch (device globals; allocation-free rule) ----------------
__device__ int   g_deg[NN];
__device__ int   g_rowptr[NN + 1];
__device__ int   g_cursor[NN];
__device__ int   g_cols[EE];
__device__ float g_dis[NN];
__device__ int   g_bsum[256];
__device__ int   g_boff[256];
__device__ __align__(16) float g_h[NN * DD];    // h' = dis[row] * (X @ W)
__device__ __align__(16) float g_agg[NN * DD];
__device__ __align__(16) float g_x[NN * DD];
__device__ float g_stats[2 * DD];
__device__ __align__(16) float g_scale[DD];
__device__ __align__(16) float g_shift[DD];

// ---------------- packed f32x2 helpers ----------------
__device__ __forceinline__ unsigned long long pack2(float x) {
    unsigned long long r;
    asm("mov.b64 %0, {%1, %1};" : "=l"(r) : "f"(x));
    return r;
}
__device__ __forceinline__ void ffma2(unsigned long long& d, unsigned long long a,
                                      unsigned long long b) {
    asm("fma.rn.f32x2 %0, %1, %2, %0;" : "+l"(d) : "l"(a), "l"(b));
}
__device__ __forceinline__ void fmul2(unsigned long long& d, unsigned long long b) {
    asm("mul.rn.f32x2 %0, %0, %1;" : "+l"(d) : "l"(b));
}

// ---------------- CSR build ----------------
__global__ void zero_kernel(int n) {
    int i = blockIdx.x * blockDim.x + threadIdx.x;
    for (int j = i; j < n; j += gridDim.x * blockDim.x) g_deg[j] = 0;
    if (i < 2 * DD) g_stats[i] = 0.0f;
}

__global__ void degree_kernel(const int* __restrict__ dst, int e) {
    int i = blockIdx.x * blockDim.x + threadIdx.x;
    if (i < e) atomicAdd(&g_deg[dst[i]], 1);
}

// scanA: per-block sums of degrees
__global__ __launch_bounds__(256) void scanA_kernel(int n) {
    __shared__ int red[8];
    int tid = threadIdx.x;
    int i = blockIdx.x * 256 + tid;
    int v = (i < n) ? g_deg[i] : 0;
    #pragma unroll
    for (int off = 16; off > 0; off >>= 1) v += __shfl_down_sync(0xffffffffu, v, off);
    if ((tid & 31) == 0) red[tid >> 5] = v;
    __syncthreads();
    if (tid < 8) {
        int s = red[tid];
        #pragma unroll
        for (int off = 4; off > 0; off >>= 1) s += __shfl_down_sync(0xffu, s, off);
        if (tid == 0) g_bsum[blockIdx.x] = s;
    }
}

// scanB: exclusive scan of <=256 block sums (one block)
__global__ __launch_bounds__(256) void scanB_kernel(int nb, int n) {
    __shared__ int wsum[8];
    int tid = threadIdx.x;
    int lane = tid & 31, wid = tid >> 5;
    int v = (tid < nb) ? g_bsum[tid] : 0;
    int incl = v;
    #pragma unroll
    for (int off = 1; off < 32; off <<= 1) {
        int t = __shfl_up_sync(0xffffffffu, incl, off);
        if (lane >= off) incl += t;
    }
    if (lane == 31) wsum[wid] = incl;
    __syncthreads();
    if (wid == 0 && lane < 8) {
        int w = wsum[lane];
        int s = w;
        #pragma unroll
        for (int off = 1; off < 8; off <<= 1) {
            int t = __shfl_up_sync(0xffu, s, off);
            if (lane >= off) s += t;
        }
        wsum[lane] = s - w;
    }
    __syncthreads();
    int excl = incl - v + wsum[wid];
    if (tid < nb) g_boff[tid] = excl;
    if (tid == nb - 1) g_rowptr[n] = excl + v;
}

// scanC: local scan + block offset -> rowptr/cursor; dis = rsqrt(deg+1)
__global__ __launch_bounds__(256) void scanC_kernel(int n) {
    __shared__ int wsum[8];
    int tid = threadIdx.x;
    int lane = tid & 31, wid = tid >> 5;
    int i = blockIdx.x * 256 + tid;
    int v = (i < n) ? g_deg[i] : 0;
    int incl = v;
    #pragma unroll
    for (int off = 1; off < 32; off <<= 1) {
        int t = __shfl_up_sync(0xffffffffu, incl, off);
        if (lane >= off) incl += t;
    }
    if (lane == 31) wsum[wid] = incl;
    __syncthreads();
    if (wid == 0 && lane < 8) {
        int w = wsum[lane];
        int s = w;
        #pragma unroll
        for (int off = 1; off < 8; off <<= 1) {
            int t = __shfl_up_sync(0xffu, s, off);
            if (lane >= off) s += t;
        }
        wsum[lane] = s - w;
    }
    __syncthreads();
    int excl = incl - v + wsum[wid] + g_boff[blockIdx.x];
    if (i < n) {
        g_rowptr[i] = excl;
        g_cursor[i] = excl;
        g_dis[i] = rsqrtf((float)v + 1.0f);
    }
}

__global__ void fill_kernel(const int* __restrict__ src, const int* __restrict__ dst, int e) {
    int i = blockIdx.x * blockDim.x + threadIdx.x;
    if (i < e) {
        int d = dst[i];
        int pos = atomicAdd(&g_cursor[d], 1);
        g_cols[pos] = src[i];
    }
}

// ---------------- GEMM: g_h = dis .* (X @ W), packed f32x2 ----------------
// block 256 = 16(tx: 8 cols) x 16(ty: 4 rows); tile 64 rows x 128 cols; K chunk 32.
// mode 0: X = Xext (plain). mode 1: fused input transform:
//   v = relu(agg*scale + shift) (+ g_x if residual); g_x = v; use v as X.
__global__ __launch_bounds__(256) void gemm_kernel(const float* __restrict__ Xext,
                                                   const float* __restrict__ W,
                                                   int n, int mode, int residual) {
    __shared__ __align__(16) unsigned long long xs[64][32];  // pre-duplicated (v,v)
    __shared__ __align__(16) float ws[32][128];
    int tid = threadIdx.x;
    int tx = tid & 15, ty = tid >> 4;
    int m0 = blockIdx.x * 64;

    unsigned long long acc[4][4];
    #pragma unroll
    for (int j = 0; j < 4; j++)
        #pragma unroll
        for (int q = 0; q < 4; q++) acc[j][q] = 0ull;

    for (int kc = 0; kc < 128; kc += 32) {
        // load X tile (64 x 32), transform if fused, store duplicated
        #pragma unroll
        for (int i = 0; i < 8; i++) {
            int lin = tid + 256 * i;
            int r = lin >> 5, c = lin & 31;
            int row = m0 + r;
            float v = 0.0f;
            if (row < n) {
                int idx = row * 128 + kc + c;
                if (mode == 0) {
                    v = Xext[idx];
                } else {
                    float a = g_agg[idx];
                    v = a * g_scale[kc + c] + g_shift[kc + c];
                    v = fmaxf(v, 0.0f);
                    if (residual) v += g_x[idx];
                    g_x[idx] = v;
                }
            }
            xs[r][c] = pack2(v);
        }
        // load W tile (32 x 128)
        #pragma unroll
        for (int i = 0; i < 4; i++) {
            int lin = tid + 256 * i;
            int r = lin >> 5, c4 = lin & 31;
            *(float4*)&ws[r][c4 * 4] = *(const float4*)&W[(kc + r) * 128 + c4 * 4];
        }
        __syncthreads();
        #pragma unroll
        for (int k = 0; k < 32; k++) {
            const ulonglong2* wp = (const ulonglong2*)&ws[k][tx * 8];
            ulonglong2 wA = wp[0];
            ulonglong2 wB = wp[1];
            #pragma unroll
            for (int j = 0; j < 4; j++) {
                unsigned long long xv = xs[ty * 4 + j][k];
                ffma2(acc[j][0], xv, wA.x);
                ffma2(acc[j][1], xv, wA.y);
                ffma2(acc[j][2], xv, wB.x);
                ffma2(acc[j][3], xv, wB.y);
            }
        }
        __syncthreads();
    }
    #pragma unroll
    for (int j = 0; j < 4; j++) {
        int row = m0 + ty * 4 + j;
        if (row < n) {
            unsigned long long dv = pack2(g_dis[row]);
            #pragma unroll
            for (int q = 0; q < 4; q++) fmul2(acc[j][q], dv);
            ulonglong2* out = (ulonglong2*)&g_h[row * 128 + tx * 8];
            out[0] = make_ulonglong2(acc[j][0], acc[j][1]);
            out[1] = make_ulonglong2(acc[j][2], acc[j][3]);
        }
    }
}

// ---------------- Aggregation (warp/node): agg = dis*(sum h'[cols] + h'[self]) + b ----------------
__global__ __launch_bounds__(256) void agg_kernel(const float* __restrict__ bias, int n) {
    __shared__ float red[8][256];
    int tid = threadIdx.x;
    int lane = tid & 31, wid = tid >> 5;
    float4 bv = *(const float4*)&bias[lane * 4];

    float ls0 = 0.f, ls1 = 0.f, ls2 = 0.f, ls3 = 0.f;
    float lq0 = 0.f, lq1 = 0.f, lq2 = 0.f, lq3 = 0.f;

    for (int node = blockIdx.x * 8 + wid; node < n; node += gridDim.x * 8) {
        int beg = __ldg(&g_rowptr[node]);
        int end = __ldg(&g_rowptr[node + 1]);
        float ax = 0.f, ay = 0.f, az = 0.f, aw = 0.f;
        int j = beg;
        for (; j + 3 < end; j += 4) {
            int c0 = __ldg(&g_cols[j]);
            int c1 = __ldg(&g_cols[j + 1]);
            int c2 = __ldg(&g_cols[j + 2]);
            int c3 = __ldg(&g_cols[j + 3]);
            float4 h0 = *(const float4*)&g_h[c0 * 128 + lane * 4];
            float4 h1 = *(const float4*)&g_h[c1 * 128 + lane * 4];
            float4 h2 = *(const float4*)&g_h[c2 * 128 + lane * 4];
            float4 h3 = *(const float4*)&g_h[c3 * 128 + lane * 4];
            ax += h0.x + h1.x + h2.x + h3.x;
            ay += h0.y + h1.y + h2.y + h3.y;
            az += h0.z + h1.z + h2.z + h3.z;
            aw += h0.w + h1.w + h2.w + h3.w;
        }
        for (; j < end; j++) {
            int c0 = __ldg(&g_cols[j]);
            float4 h0 = *(const float4*)&g_h[c0 * 128 + lane * 4];
            ax += h0.x; ay += h0.y; az += h0.z; aw += h0.w;
        }
        float4 hs = *(const float4*)&g_h[node * 128 + lane * 4];
        float dn = __ldg(&g_dis[node]);
        ax = dn * (ax + hs.x) + bv.x;
        ay = dn * (ay + hs.y) + bv.y;
        az = dn * (az + hs.z) + bv.z;
        aw = dn * (aw + hs.w) + bv.w;
        *(float4*)&g_agg[node * 128 + lane * 4] = make_float4(ax, ay, az, aw);

        ls0 += ax; ls1 += ay; ls2 += az; ls3 += aw;
        lq0 += ax * ax; lq1 += ay * ay; lq2 += az * az; lq3 += aw * aw;
    }

    red[wid][lane * 4 + 0] = ls0;
    red[wid][lane * 4 + 1] = ls1;
    red[wid][lane * 4 + 2] = ls2;
    red[wid][lane * 4 + 3] = ls3;
    __syncthreads();
    float tot = 0.f;
    #pragma unroll
    for (int w = 0; w < 8; w++) tot += red[w][tid];
    if (tid < 128) atomicAdd(&g_stats[tid], tot);
    __syncthreads();
    red[wid][lane * 4 + 0] = lq0;
    red[wid][lane * 4 + 1] = lq1;
    red[wid][lane * 4 + 2] = lq2;
    red[wid][lane * 4 + 3] = lq3;
    __syncthreads();
    tot = 0.f;
    #pragma unroll
    for (int w = 0; w < 8; w++) tot += red[w][tid];
    if (tid < 128) atomicAdd(&g_stats[128 + tid], tot);
}

// ---------------- BN finalize ----------------
__global__ void finalize_kernel(const float* __restrict__ gamma, const float* __restrict__ beta,
                                float invn) {
    int c = threadIdx.x;  // 128
    float s  = g_stats[c];
    float sq = g_stats[128 + c];
    float mean = s * invn;
    float var  = sq * invn - mean * mean;
    float istd = rsqrtf(var + 1e-5f);
    float sc = gamma[c] * istd;
    g_scale[c] = sc;
    g_shift[c] = beta[c] - mean * sc;
    g_stats[c] = 0.f;
    g_stats[128 + c] = 0.f;
}

// ---------------- Final elementwise: out = x2 + bn(agg2), no relu ----------------
__global__ __launch_bounds__(256) void elem_final_kernel(float* __restrict__ out, int n4) {
    int idx = blockIdx.x * blockDim.x + threadIdx.x;
    if (idx >= n4) return;
    int c4 = idx & 31;
    float4 sc = ((const float4*)g_scale)[c4];
    float4 sh = ((const float4*)g_shift)[c4];
    float4 a  = ((const float4*)g_agg)[idx];
    float4 r  = ((const float4*)g_x)[idx];
    float4 y;
    y.x = a.x * sc.x + sh.x + r.x;
    y.y = a.y * sc.y + sh.y + r.y;
    y.z = a.z * sc.z + sh.z + r.z;
    y.w = a.w * sc.w + sh.w + r.w;
    ((float4*)out)[idx] = y;
}

// ---------------- launch ----------------
extern "C" void kernel_launch(void* const* d_in, const int* in_sizes, int n_in,
                              void* d_out, int out_size) {
    const float* x      = (const float*)d_in[0];
    const int*   ei     = (const int*)d_in[1];
    const float* Ws     = (const float*)d_in[2];
    const float* bs     = (const float*)d_in[3];
    const float* gammas = (const float*)d_in[4];
    const float* betas  = (const float*)d_in[5];

    int n = in_sizes[0] / DD;   // 50000
    int e = in_sizes[1] / 2;    // 800000
    const int* src = ei;
    const int* dst = ei + e;
    int nb = (n + 255) / 256;

    zero_kernel<<<196, 256>>>(n);
    degree_kernel<<<(e + 255) / 256, 256>>>(dst, e);
    scanA_kernel<<<nb, 256>>>(n);
    scanB_kernel<<<1, 256>>>(nb, n);
    scanC_kernel<<<nb, 256>>>(n);
    fill_kernel<<<(e + 255) / 256, 256>>>(src, dst, e);

    float invn = 1.0f / (float)n;
    int n4 = n * (DD / 4);
    int gemm_grid = (n + 63) / 64;
    int agg_grid = 1184;

    for (int l = 0; l < 3; l++) {
        int mode = (l > 0) ? 1 : 0;
        int residual = (l > 1) ? 1 : 0;
        gemm_kernel<<<gemm_grid, 256>>>(x, Ws + l * DD * DD, n, mode, residual);
        agg_kernel<<<agg_grid, 256>>>(bs + l * DD, n);
        finalize_kernel<<<1, 128>>>(gammas + l * DD, betas + l * DD, invn);
    }
    elem_final_kernel<<<(n4 + 255) / 256, 256>>>((float*)d_out, n4);
}

// round 9
// speedup vs baseline: 1.2413x; 1.2413x over previous
#include <cuda_runtime.h>
#include <math.h>

#define NN 50000
#define EE 800000
#define DD 128

// ---------------- scratch (device globals; allocation-free rule) ----------------
__device__ int   g_deg[NN];
__device__ int   g_rowptr[NN + 1];
__device__ int   g_cursor[NN];
__device__ int   g_cols[EE];
__device__ float g_dis[NN];
__device__ int   g_bsum[256];
__device__ int   g_boff[256];
__device__ __align__(16) float g_h[NN * DD];    // h' = dis[row] * (X @ W)
__device__ __align__(16) float g_agg[NN * DD];
__device__ __align__(16) float g_x[NN * DD];
__device__ float g_stats[2 * DD];
__device__ __align__(16) float g_scale[DD];
__device__ __align__(16) float g_shift[DD];

// ---------------- CSR build ----------------
__global__ void zero_kernel(int n) {
    int i = blockIdx.x * blockDim.x + threadIdx.x;
    for (int j = i; j < n; j += gridDim.x * blockDim.x) g_deg[j] = 0;
    if (i < 2 * DD) g_stats[i] = 0.0f;
}

__global__ void degree_kernel(const int* __restrict__ dst, int e) {
    int i = blockIdx.x * blockDim.x + threadIdx.x;
    if (i < e) atomicAdd(&g_deg[dst[i]], 1);
}

// scanA: per-block sums of degrees
__global__ __launch_bounds__(256) void scanA_kernel(int n) {
    __shared__ int red[8];
    int tid = threadIdx.x;
    int i = blockIdx.x * 256 + tid;
    int v = (i < n) ? g_deg[i] : 0;
    #pragma unroll
    for (int off = 16; off > 0; off >>= 1) v += __shfl_down_sync(0xffffffffu, v, off);
    if ((tid & 31) == 0) red[tid >> 5] = v;
    __syncthreads();
    if (tid < 8) {
        int s = red[tid];
        #pragma unroll
        for (int off = 4; off > 0; off >>= 1) s += __shfl_down_sync(0xffu, s, off);
        if (tid == 0) g_bsum[blockIdx.x] = s;
    }
}

// scanB: exclusive scan of <=256 block sums (one block)
__global__ __launch_bounds__(256) void scanB_kernel(int nb, int n) {
    __shared__ int wsum[8];
    int tid = threadIdx.x;
    int lane = tid & 31, wid = tid >> 5;
    int v = (tid < nb) ? g_bsum[tid] : 0;
    int incl = v;
    #pragma unroll
    for (int off = 1; off < 32; off <<= 1) {
        int t = __shfl_up_sync(0xffffffffu, incl, off);
        if (lane >= off) incl += t;
    }
    if (lane == 31) wsum[wid] = incl;
    __syncthreads();
    if (wid == 0 && lane < 8) {
        int w = wsum[lane];
        int s = w;
        #pragma unroll
        for (int off = 1; off < 8; off <<= 1) {
            int t = __shfl_up_sync(0xffu, s, off);
            if (lane >= off) s += t;
        }
        wsum[lane] = s - w;
    }
    __syncthreads();
    int excl = incl - v + wsum[wid];
    if (tid < nb) g_boff[tid] = excl;
    if (tid == nb - 1) g_rowptr[n] = excl + v;
}

// scanC: local scan + block offset -> rowptr/cursor; dis = rsqrt(deg+1)
__global__ __launch_bounds__(256) void scanC_kernel(int n) {
    __shared__ int wsum[8];
    int tid = threadIdx.x;
    int lane = tid & 31, wid = tid >> 5;
    int i = blockIdx.x * 256 + tid;
    int v = (i < n) ? g_deg[i] : 0;
    int incl = v;
    #pragma unroll
    for (int off = 1; off < 32; off <<= 1) {
        int t = __shfl_up_sync(0xffffffffu, incl, off);
        if (lane >= off) incl += t;
    }
    if (lane == 31) wsum[wid] = incl;
    __syncthreads();
    if (wid == 0 && lane < 8) {
        int w = wsum[lane];
        int s = w;
        #pragma unroll
        for (int off = 1; off < 8; off <<= 1) {
            int t = __shfl_up_sync(0xffu, s, off);
            if (lane >= off) s += t;
        }
        wsum[lane] = s - w;
    }
    __syncthreads();
    int excl = incl - v + wsum[wid] + g_boff[blockIdx.x];
    if (i < n) {
        g_rowptr[i] = excl;
        g_cursor[i] = excl;
        g_dis[i] = rsqrtf((float)v + 1.0f);
    }
}

__global__ void fill_kernel(const int* __restrict__ src, const int* __restrict__ dst, int e) {
    int i = blockIdx.x * blockDim.x + threadIdx.x;
    if (i < e) {
        int d = dst[i];
        int pos = atomicAdd(&g_cursor[d], 1);
        g_cols[pos] = src[i];
    }
}

// ---------------- GEMM: g_h = dis .* (X @ W)  (round-1 proven fp32 core) ----------------
// block = 256 threads (tx=32 lanes over 128 cols via float4, ty=8 row groups),
// tile 64 rows x 128 cols, K chunked by 32.
// mode 0: X = Xext. mode 1: fused BN-apply from previous layer:
//   v = relu(agg*scale + shift) (+ g_x if residual); g_x = v; use v as X.
__global__ __launch_bounds__(256) void gemm_kernel(const float* __restrict__ Xext,
                                                   const float* __restrict__ W,
                                                   int n, int mode, int residual) {
    __shared__ __align__(16) float xs[64][32];
    __shared__ __align__(16) float ws[32][128];
    int tid = threadIdx.x;
    int tx = tid & 31, ty = tid >> 5;
    int m0 = blockIdx.x * 64;

    float4 acc[8];
    #pragma unroll
    for (int j = 0; j < 8; j++) acc[j] = make_float4(0.f, 0.f, 0.f, 0.f);

    for (int kc = 0; kc < 128; kc += 32) {
        // load X tile (64 x 32); fused BN/relu/residual transform when mode==1
        #pragma unroll
        for (int i = 0; i < 8; i++) {
            int lin = tid + 256 * i;
            int r = lin >> 5, c = lin & 31;
            int row = m0 + r;
            float v = 0.0f;
            if (row < n) {
                int idx = row * 128 + kc + c;
                if (mode == 0) {
                    v = Xext[idx];
                } else {
                    float a = g_agg[idx];
                    v = a * g_scale[kc + c] + g_shift[kc + c];
                    v = fmaxf(v, 0.0f);
                    if (residual) v += g_x[idx];
                    g_x[idx] = v;
                }
            }
            xs[r][c] = v;
        }
        // load W tile (32 x 128)
        #pragma unroll
        for (int i = 0; i < 4; i++) {
            int lin = tid + 256 * i;
            int r = lin >> 5, c4 = lin & 31;
            *(float4*)&ws[r][c4 * 4] = *(const float4*)&W[(kc + r) * 128 + c4 * 4];
        }
        __syncthreads();
        #pragma unroll
        for (int k = 0; k < 32; k++) {
            float4 wv = *(const float4*)&ws[k][tx * 4];
            #pragma unroll
            for (int j = 0; j < 8; j++) {
                float xv = xs[ty * 8 + j][k];
                acc[j].x += xv * wv.x;
                acc[j].y += xv * wv.y;
                acc[j].z += xv * wv.z;
                acc[j].w += xv * wv.w;
            }
        }
        __syncthreads();
    }
    #pragma unroll
    for (int j = 0; j < 8; j++) {
        int row = m0 + ty * 8 + j;
        if (row < n) {
            float dn = g_dis[row];
            acc[j].x *= dn; acc[j].y *= dn; acc[j].z *= dn; acc[j].w *= dn;
            *(float4*)&g_h[row * 128 + tx * 4] = acc[j];
        }
    }
}

// ---------------- Aggregation (warp/node): agg = dis*(sum h'[cols] + h'[self]) + b ----------------
__global__ __launch_bounds__(256) void agg_kernel(const float* __restrict__ bias, int n) {
    __shared__ float red[8][256];
    int tid = threadIdx.x;
    int lane = tid & 31, wid = tid >> 5;
    float4 bv = *(const float4*)&bias[lane * 4];

    float ls0 = 0.f, ls1 = 0.f, ls2 = 0.f, ls3 = 0.f;
    float lq0 = 0.f, lq1 = 0.f, lq2 = 0.f, lq3 = 0.f;

    for (int node = blockIdx.x * 8 + wid; node < n; node += gridDim.x * 8) {
        int beg = __ldg(&g_rowptr[node]);
        int end = __ldg(&g_rowptr[node + 1]);
        float ax = 0.f, ay = 0.f, az = 0.f, aw = 0.f;
        int j = beg;
        for (; j + 3 < end; j += 4) {
            int c0 = __ldg(&g_cols[j]);
            int c1 = __ldg(&g_cols[j + 1]);
            int c2 = __ldg(&g_cols[j + 2]);
            int c3 = __ldg(&g_cols[j + 3]);
            float4 h0 = *(const float4*)&g_h[c0 * 128 + lane * 4];
            float4 h1 = *(const float4*)&g_h[c1 * 128 + lane * 4];
            float4 h2 = *(const float4*)&g_h[c2 * 128 + lane * 4];
            float4 h3 = *(const float4*)&g_h[c3 * 128 + lane * 4];
            ax += h0.x + h1.x + h2.x + h3.x;
            ay += h0.y + h1.y + h2.y + h3.y;
            az += h0.z + h1.z + h2.z + h3.z;
            aw += h0.w + h1.w + h2.w + h3.w;
        }
        for (; j < end; j++) {
            int c0 = __ldg(&g_cols[j]);
            float4 h0 = *(const float4*)&g_h[c0 * 128 + lane * 4];
            ax += h0.x; ay += h0.y; az += h0.z; aw += h0.w;
        }
        float4 hs = *(const float4*)&g_h[node * 128 + lane * 4];
        float dn = __ldg(&g_dis[node]);
        ax = dn * (ax + hs.x) + bv.x;
        ay = dn * (ay + hs.y) + bv.y;
        az = dn * (az + hs.z) + bv.z;
        aw = dn * (aw + hs.w) + bv.w;
        *(float4*)&g_agg[node * 128 + lane * 4] = make_float4(ax, ay, az, aw);

        ls0 += ax; ls1 += ay; ls2 += az; ls3 += aw;
        lq0 += ax * ax; lq1 += ay * ay; lq2 += az * az; lq3 += aw * aw;
    }

    red[wid][lane * 4 + 0] = ls0;
    red[wid][lane * 4 + 1] = ls1;
    red[wid][lane * 4 + 2] = ls2;
    red[wid][lane * 4 + 3] = ls3;
    __syncthreads();
    float tot = 0.f;
    #pragma unroll
    for (int w = 0; w < 8; w++) tot += red[w][tid];
    if (tid < 128) atomicAdd(&g_stats[tid], tot);
    __syncthreads();
    red[wid][lane * 4 + 0] = lq0;
    red[wid][lane * 4 + 1] = lq1;
    red[wid][lane * 4 + 2] = lq2;
    red[wid][lane * 4 + 3] = lq3;
    __syncthreads();
    tot = 0.f;
    #pragma unroll
    for (int w = 0; w < 8; w++) tot += red[w][tid];
    if (tid < 128) atomicAdd(&g_stats[128 + tid], tot);
}

// ---------------- BN finalize ----------------
__global__ void finalize_kernel(const float* __restrict__ gamma, const float* __restrict__ beta,
                                float invn) {
    int c = threadIdx.x;  // 128
    float s  = g_stats[c];
    float sq = g_stats[128 + c];
    float mean = s * invn;
    float var  = sq * invn - mean * mean;
    float istd = rsqrtf(var + 1e-5f);
    float sc = gamma[c] * istd;
    g_scale[c] = sc;
    g_shift[c] = beta[c] - mean * sc;
    g_stats[c] = 0.f;
    g_stats[128 + c] = 0.f;
}

// ---------------- Final elementwise: out = x2 + bn(agg2), no relu ----------------
__global__ __launch_bounds__(256) void elem_final_kernel(float* __restrict__ out, int n4) {
    int idx = blockIdx.x * blockDim.x + threadIdx.x;
    if (idx >= n4) return;
    int c4 = idx & 31;
    float4 sc = ((const float4*)g_scale)[c4];
    float4 sh = ((const float4*)g_shift)[c4];
    float4 a  = ((const float4*)g_agg)[idx];
    float4 r  = ((const float4*)g_x)[idx];
    float4 y;
    y.x = a.x * sc.x + sh.x + r.x;
    y.y = a.y * sc.y + sh.y + r.y;
    y.z = a.z * sc.z + sh.z + r.z;
    y.w = a.w * sc.w + sh.w + r.w;
    ((float4*)out)[idx] = y;
}

// ---------------- launch ----------------
extern "C" void kernel_launch(void* const* d_in, const int* in_sizes, int n_in,
                              void* d_out, int out_size) {
    const float* x      = (const float*)d_in[0];
    const int*   ei     = (const int*)d_in[1];
    const float* Ws     = (const float*)d_in[2];
    const float* bs     = (const float*)d_in[3];
    const float* gammas = (const float*)d_in[4];
    const float* betas  = (const float*)d_in[5];

    int n = in_sizes[0] / DD;   // 50000
    int e = in_sizes[1] / 2;    // 800000
    const int* src = ei;
    const int* dst = ei + e;
    int nb = (n + 255) / 256;

    zero_kernel<<<196, 256>>>(n);
    degree_kernel<<<(e + 255) / 256, 256>>>(dst, e);
    scanA_kernel<<<nb, 256>>>(n);
    scanB_kernel<<<1, 256>>>(nb, n);
    scanC_kernel<<<nb, 256>>>(n);
    fill_kernel<<<(e + 255) / 256, 256>>>(src, dst, e);

    float invn = 1.0f / (float)n;
    int n4 = n * (DD / 4);
    int gemm_grid = (n + 63) / 64;
    int agg_grid = 1184;

    for (int l = 0; l < 3; l++) {
        int mode = (l > 0) ? 1 : 0;
        int residual = (l > 1) ? 1 : 0;
        gemm_kernel<<<gemm_grid, 256>>>(x, Ws + l * DD * DD, n, mode, residual);
        agg_kernel<<<agg_grid, 256>>>(bs + l * DD, n);
        finalize_kernel<<<1, 128>>>(gammas + l * DD, betas + l * DD, invn);
    }
    elem_final_kernel<<<(n4 + 255) / 256, 256>>>((float*)d_out, n4);
}